// round 3
// baseline (speedup 1.0000x reference)
#include <cuda_runtime.h>
#include <math.h>

// Problem constants
constexpr int cN = 40000, cE = 400000, cG = 512;
constexpr int cHID = 192, cHEADS = 4, cDH = 48, cFFN = 384, cL = 3;

// ---------------- scratch (device globals; no allocation allowed) ----------
__device__ float g_h[cN * cHID];
__device__ float g_q[cN * cHID];   // reused as edge-head A
__device__ float g_k[cN * cHID];   // reused as edge-head B
__device__ float g_v[cN * cHID];
__device__ float g_msg[cN * cHID];
__device__ float g_t1[cN * cFFN];
__device__ float g_t2[cN * cHID];
__device__ int   g_deg[cN];
__device__ int   g_rowptr[cN + 1];
__device__ int   g_cursor[cN];
__device__ int   g_csrc[cE];
__device__ int   g_ceid[cE];

// ---------------- CSR build ------------------------------------------------
__global__ void deg_kernel(const int* __restrict__ ei) {
    int e = blockIdx.x * blockDim.x + threadIdx.x;
    if (e < cE) atomicAdd(&g_deg[ei[cE + e]], 1);
}

__global__ void scan_kernel() {
    __shared__ int sh[1024];
    __shared__ int carry;
    int tid = threadIdx.x;
    if (tid == 0) carry = 0;
    __syncthreads();
    for (int base = 0; base < cN; base += 1024) {
        int i = base + tid;
        int v = (i < cN) ? g_deg[i] : 0;
        sh[tid] = v;
        __syncthreads();
        for (int off = 1; off < 1024; off <<= 1) {
            int t = (tid >= off) ? sh[tid - off] : 0;
            __syncthreads();
            sh[tid] += t;
            __syncthreads();
        }
        if (i < cN) g_rowptr[i + 1] = carry + sh[tid];
        __syncthreads();
        if (tid == 0) carry += sh[1023];
        __syncthreads();
    }
    if (tid == 0) g_rowptr[0] = 0;
}

__global__ void fill_kernel(const int* __restrict__ ei) {
    int e = blockIdx.x * blockDim.x + threadIdx.x;
    if (e < cE) {
        int d = ei[cE + e];
        int pos = atomicAdd(&g_cursor[d], 1);
        int slot = g_rowptr[d] + pos;
        g_csrc[slot] = ei[e];
        g_ceid[slot] = e;
    }
}

// ---------------- input embedding -----------------------------------------
__global__ void input_kernel(const float* __restrict__ x,
                             const int* __restrict__ batch,
                             const int* __restrict__ gptr,
                             const int* __restrict__ tg,
                             const float* __restrict__ gp,
                             const float* __restrict__ sp,
                             const float* __restrict__ ep,
                             const float* __restrict__ W,
                             const float* __restrict__ b) {
    int n = blockIdx.x;
    int j = threadIdx.x;  // 192
    __shared__ float f[16];
    __shared__ int sgid;
    if (j == 0) {
        int gid = gptr[batch[n]] + tg[n];
        gid = gid < 0 ? 0 : (gid > cG - 1 ? cG - 1 : gid);
        sgid = gid;
    }
    __syncthreads();
    if (j < 16) {
        float val;
        if (j < 4)       val = x[n * 4 + j];
        else if (j < 7)  val = gp[sgid * 3 + (j - 4)];
        else if (j < 10) val = sp[n * 3 + (j - 7)];
        else             val = ep[sgid * 6 + (j - 10)];
        f[j] = val;
    }
    __syncthreads();
    float acc = b[j];
#pragma unroll
    for (int i = 0; i < 16; i++) acc += f[i] * W[i * cHID + j];
    g_h[n * cHID + j] = acc;
}

// ---------------- generic tiled fp32 GEMM: C = A(MxK) * B(KxN) [+bias][relu]
// K % 16 == 0, N % 64 == 0 guaranteed by call sites.
__global__ __launch_bounds__(256) void gemm_kernel(
    const float* __restrict__ A, const float* __restrict__ B,
    float* __restrict__ C, int M, int K, int N, int ldb,
    const float* __restrict__ bias, int relu) {
    constexpr int BM = 64, BN = 64, BK = 16;
    __shared__ float As[BK][BM];
    __shared__ float Bs[BK][BN];
    int tid = threadIdx.x;
    int tx = tid & 15, ty = tid >> 4;
    int m0 = blockIdx.x * BM, n0 = blockIdx.y * BN;
    float acc[4][4] = {};
    int aRow = tid >> 2;          // 0..63
    int aCol = (tid & 3) * 4;     // 0,4,8,12
    int bRow = tid >> 4;          // 0..15
    int bCol = (tid & 15) * 4;    // 0..60

    for (int k0 = 0; k0 < K; k0 += BK) {
        float4 av = make_float4(0.f, 0.f, 0.f, 0.f);
        int m = m0 + aRow;
        if (m < M) av = *(const float4*)(A + (size_t)m * K + k0 + aCol);
        As[aCol + 0][aRow] = av.x;
        As[aCol + 1][aRow] = av.y;
        As[aCol + 2][aRow] = av.z;
        As[aCol + 3][aRow] = av.w;
        float4 bv = *(const float4*)(B + (size_t)(k0 + bRow) * ldb + n0 + bCol);
        *(float4*)(&Bs[bRow][bCol]) = bv;
        __syncthreads();
#pragma unroll
        for (int kk = 0; kk < BK; ++kk) {
            float a[4];
#pragma unroll
            for (int i = 0; i < 4; i++) a[i] = As[kk][ty * 4 + i];
            float4 b4 = *(const float4*)(&Bs[kk][tx * 4]);
            float bb[4] = {b4.x, b4.y, b4.z, b4.w};
#pragma unroll
            for (int i = 0; i < 4; i++)
#pragma unroll
                for (int jj = 0; jj < 4; jj++) acc[i][jj] += a[i] * bb[jj];
        }
        __syncthreads();
    }
#pragma unroll
    for (int i = 0; i < 4; i++) {
        int m = m0 + ty * 4 + i;
        if (m >= M) continue;
#pragma unroll
        for (int jj = 0; jj < 4; jj++) {
            int nn = n0 + tx * 4 + jj;
            float v = acc[i][jj];
            if (bias) v += bias[nn];
            if (relu) v = fmaxf(v, 0.f);
            C[(size_t)m * N + nn] = v;
        }
    }
}

// ---------------- edge-softmax attention (gather, online softmax) ----------
// one warp per (node, head); lane covers dims {lane, lane+32(<48)}
__global__ void attn_kernel(const float* __restrict__ ea,
                            const float* __restrict__ We) {
    int w = blockIdx.x * 8 + (threadIdx.x >> 5);
    int lane = threadIdx.x & 31;
    int n = w >> 2, h = w & 3;
    const float scale = 0.14433756729740643f;  // 1/sqrt(48)
    int off = n * cHID + h * cDH;
    float q0 = g_q[off + lane];
    float q1 = (lane < 16) ? g_q[off + 32 + lane] : 0.f;
    float We0[4], We1[4];
#pragma unroll
    for (int i = 0; i < 4; i++) {
        We0[i] = We[i * cHID + h * cDH + lane];
        We1[i] = (lane < 16) ? We[i * cHID + h * cDH + 32 + lane] : 0.f;
    }
    float m = -1e30f, den = 0.f, a0 = 0.f, a1 = 0.f;
    int beg = g_rowptr[n], end = g_rowptr[n + 1];
    for (int idx = beg; idx < end; ++idx) {
        int s = g_csrc[idx];
        int eid = g_ceid[idx];
        float ea0 = ea[eid * 4 + 0], ea1 = ea[eid * 4 + 1];
        float ea2 = ea[eid * 4 + 2], ea3 = ea[eid * 4 + 3];
        float e0 = ea0 * We0[0] + ea1 * We0[1] + ea2 * We0[2] + ea3 * We0[3];
        float e1 = ea0 * We1[0] + ea1 * We1[1] + ea2 * We1[2] + ea3 * We1[3];
        int so = s * cHID + h * cDH;
        float k0 = g_k[so + lane] + e0;
        float k1 = (lane < 16) ? (g_k[so + 32 + lane] + e1) : 0.f;
        float p = q0 * k0 + q1 * k1;
#pragma unroll
        for (int o = 16; o; o >>= 1) p += __shfl_xor_sync(0xffffffffu, p, o);
        float logit = p * scale;
        float mn = fmaxf(m, logit);
        float corr = __expf(m - mn);
        float wg = __expf(logit - mn);
        float v0 = g_v[so + lane] + e0;
        float v1 = (lane < 16) ? (g_v[so + 32 + lane] + e1) : 0.f;
        a0 = a0 * corr + wg * v0;
        a1 = a1 * corr + wg * v1;
        den = den * corr + wg;
        m = mn;
    }
    float inv = 1.f / (den + 1e-16f);
    g_msg[off + lane] = a0 * inv;
    if (lane < 16) g_msg[off + 32 + lane] = a1 * inv;
}

// ---------------- residual + (opt bias) + LayerNorm over 192 ---------------
__global__ void ln_kernel(float* __restrict__ h, const float* __restrict__ add,
                          const float* __restrict__ bias,
                          const float* __restrict__ g, const float* __restrict__ b) {
    int n = blockIdx.x, j = threadIdx.x;  // 192
    __shared__ float red[192];
    __shared__ float s_mean, s_rstd;
    float v = h[n * cHID + j] + add[n * cHID + j];
    if (bias) v += bias[j];
    red[j] = v;
    __syncthreads();
    if (j < 64) red[j] += red[j + 64] + red[j + 128];
    __syncthreads();
    if (j < 32) {
        float t = red[j] + red[j + 32];
#pragma unroll
        for (int o = 16; o; o >>= 1) t += __shfl_xor_sync(0xffffffffu, t, o);
        if (j == 0) s_mean = t * (1.f / 192.f);
    }
    __syncthreads();
    float d = v - s_mean;
    red[j] = d * d;
    __syncthreads();
    if (j < 64) red[j] += red[j + 64] + red[j + 128];
    __syncthreads();
    if (j < 32) {
        float t = red[j] + red[j + 32];
#pragma unroll
        for (int o = 16; o; o >>= 1) t += __shfl_xor_sync(0xffffffffu, t, o);
        if (j == 0) s_rstd = rsqrtf(t * (1.f / 192.f) + 1e-5f);
    }
    __syncthreads();
    h[n * cHID + j] = d * s_rstd * g[j] + b[j];
}

// ---------------- fused edge head MLP --------------------------------------
// z1 = relu(A[src]+B[dst]+ea@W_e1[384:388]); z2 = relu(z1@W_e2+b); out = z2@W_e3+b
__global__ __launch_bounds__(192) void edge_out_kernel(
    const float* __restrict__ Ae, const float* __restrict__ Be,
    const float* __restrict__ edge_attr, const int* __restrict__ ei,
    const float* __restrict__ W_e1, const float* __restrict__ W_e2,
    const float* __restrict__ b_e2, const float* __restrict__ W_e3,
    const float* __restrict__ b_e3, float* __restrict__ out) {
    int e = blockIdx.x;
    int j = threadIdx.x;  // 192
    __shared__ float z1[192];
    __shared__ float red[192];
    int s = ei[e], d = ei[cE + e];
    float ea0 = edge_attr[e * 4 + 0], ea1 = edge_attr[e * 4 + 1];
    float ea2 = edge_attr[e * 4 + 2], ea3 = edge_attr[e * 4 + 3];
    float z = Ae[s * cHID + j] + Be[d * cHID + j]
            + ea0 * W_e1[384 * cHID + j] + ea1 * W_e1[385 * cHID + j]
            + ea2 * W_e1[386 * cHID + j] + ea3 * W_e1[387 * cHID + j];
    z1[j] = fmaxf(z, 0.f);
    __syncthreads();
    int o = j % 96;
    int half = j / 96;
    int base = half * 96;
    float acc = 0.f;
#pragma unroll 4
    for (int jj = 0; jj < 96; jj++) acc += z1[base + jj] * W_e2[(base + jj) * 96 + o];
    red[j] = acc;
    __syncthreads();
    if (j < 96) {
        float z2 = fmaxf(red[j] + red[j + 96] + b_e2[j], 0.f);
        red[j] = z2 * W_e3[j];
    }
    __syncthreads();
    if (j < 32) {
        float t = red[j] + red[j + 32] + red[j + 64];
#pragma unroll
        for (int off = 16; off; off >>= 1) t += __shfl_xor_sync(0xffffffffu, t, off);
        if (j == 0) out[e] = t + b_e3[0];
    }
}

// ---------------- host -----------------------------------------------------
extern "C" void kernel_launch(void* const* d_in, const int* in_sizes, int n_in,
                              void* d_out, int out_size) {
    const float* x        = (const float*)d_in[0];
    const int*   ei       = (const int*)d_in[1];
    const float* eattr    = (const float*)d_in[2];
    const int*   batch    = (const int*)d_in[3];
    const int*   gptr     = (const int*)d_in[4];
    const int*   tg       = (const int*)d_in[5];
    const float* gp       = (const float*)d_in[6];
    const float* sp       = (const float*)d_in[7];
    const float* ep       = (const float*)d_in[8];
    const float* W_in     = (const float*)d_in[9];
    const float* b_in     = (const float*)d_in[10];
    const float* Wq       = (const float*)d_in[11];
    const float* Wk       = (const float*)d_in[12];
    const float* Wv       = (const float*)d_in[13];
    const float* We       = (const float*)d_in[14];
    const float* Wo       = (const float*)d_in[15];
    const float* bo       = (const float*)d_in[16];
    const float* ln1_g    = (const float*)d_in[17];
    const float* ln1_b    = (const float*)d_in[18];
    const float* W_ff1    = (const float*)d_in[19];
    const float* b_ff1    = (const float*)d_in[20];
    const float* W_ff2    = (const float*)d_in[21];
    const float* b_ff2    = (const float*)d_in[22];
    const float* ln2_g    = (const float*)d_in[23];
    const float* ln2_b    = (const float*)d_in[24];
    const float* W_e1     = (const float*)d_in[25];
    const float* b_e1     = (const float*)d_in[26];
    const float* W_e2     = (const float*)d_in[27];
    const float* b_e2     = (const float*)d_in[28];
    const float* W_e3     = (const float*)d_in[29];
    const float* b_e3     = (const float*)d_in[30];
    float* out = (float*)d_out;

    float *hb, *qb, *kb, *vb, *msgb, *t1, *t2;
    int *deg, *cursor;
    cudaGetSymbolAddress((void**)&hb, g_h);
    cudaGetSymbolAddress((void**)&qb, g_q);
    cudaGetSymbolAddress((void**)&kb, g_k);
    cudaGetSymbolAddress((void**)&vb, g_v);
    cudaGetSymbolAddress((void**)&msgb, g_msg);
    cudaGetSymbolAddress((void**)&t1, g_t1);
    cudaGetSymbolAddress((void**)&t2, g_t2);
    cudaGetSymbolAddress((void**)&deg, g_deg);
    cudaGetSymbolAddress((void**)&cursor, g_cursor);

    auto gemm = [&](const float* A, const float* B, float* C, int M, int K,
                    int Nc, int ldb, const float* bias, int relu) {
        dim3 grid((M + 63) / 64, Nc / 64);
        gemm_kernel<<<grid, 256>>>(A, B, C, M, K, Nc, ldb, bias, relu);
    };

    // CSR over dst (rebuilt every call; deterministic work)
    cudaMemsetAsync(deg, 0, cN * sizeof(int));
    cudaMemsetAsync(cursor, 0, cN * sizeof(int));
    deg_kernel<<<(cE + 255) / 256, 256>>>(ei);
    scan_kernel<<<1, 1024>>>();
    fill_kernel<<<(cE + 255) / 256, 256>>>(ei);

    // input embedding
    input_kernel<<<cN, 192>>>(x, batch, gptr, tg, gp, sp, ep, W_in, b_in);

    for (int l = 0; l < cL; l++) {
        const float* Wq_l = Wq + l * cHID * cHID;
        const float* Wk_l = Wk + l * cHID * cHID;
        const float* Wv_l = Wv + l * cHID * cHID;
        const float* We_l = We + l * 4 * cHID;
        const float* Wo_l = Wo + l * cHID * cHID;
        const float* bo_l = bo + l * cHID;
        const float* W1_l = W_ff1 + l * cHID * cFFN;
        const float* b1_l = b_ff1 + l * cFFN;
        const float* W2_l = W_ff2 + l * cFFN * cHID;
        const float* b2_l = b_ff2 + l * cHID;

        gemm(hb, Wq_l, qb, cN, cHID, cHID, cHID, nullptr, 0);
        gemm(hb, Wk_l, kb, cN, cHID, cHID, cHID, nullptr, 0);
        gemm(hb, Wv_l, vb, cN, cHID, cHID, cHID, nullptr, 0);
        attn_kernel<<<cN * cHEADS / 8, 256>>>(eattr, We_l);
        gemm(msgb, Wo_l, t2, cN, cHID, cHID, cHID, nullptr, 0);
        ln_kernel<<<cN, 192>>>(hb, t2, bo_l, ln1_g + l * cHID, ln1_b + l * cHID);
        gemm(hb, W1_l, t1, cN, cHID, cFFN, cFFN, b1_l, 1);
        gemm(t1, W2_l, t2, cN, cFFN, cHID, cHID, b2_l, 0);
        ln_kernel<<<cN, 192>>>(hb, t2, nullptr, ln2_g + l * cHID, ln2_b + l * cHID);
    }

    // edge head: A = h@W_e1[0:192]+b_e1 ; B = h@W_e1[192:384]
    gemm(hb, W_e1, qb, cN, cHID, cHID, cHID, b_e1, 0);
    gemm(hb, W_e1 + 192 * cHID, kb, cN, cHID, cHID, cHID, nullptr, 0);
    edge_out_kernel<<<cE, 192>>>(qb, kb, eattr, ei, W_e1, W_e2, b_e2, W_e3, b_e3, out);
}

// round 5
// speedup vs baseline: 1.9669x; 1.9669x over previous
#include <cuda_runtime.h>
#include <cuda_fp16.h>
#include <cstdint>
#include <math.h>

// Problem constants
constexpr int cN = 40000, cE = 400000, cG = 512;
constexpr int cHID = 192, cHEADS = 4, cDH = 48, cFFN = 384, cL = 3;

__device__ __forceinline__ uint32_t smem_to_u32(const void* p) {
    uint32_t a;
    asm("{ .reg .u64 t; cvta.to.shared.u64 t, %1; cvt.u32.u64 %0, t; }" : "=r"(a) : "l"(p));
    return a;
}
__device__ __forceinline__ void cpa16(uint32_t dst, const void* src, bool v) {
    int sz = v ? 16 : 0;
    asm volatile("cp.async.cg.shared.global [%0], [%1], 16, %2;"
                 :: "r"(dst), "l"(src), "r"(sz));
}
__device__ __forceinline__ void ldm4(uint32_t* r, uint32_t a) {
    asm volatile("ldmatrix.sync.aligned.m8n8.x4.shared.b16 {%0,%1,%2,%3}, [%4];"
        : "=r"(r[0]), "=r"(r[1]), "=r"(r[2]), "=r"(r[3]) : "r"(a));
}
__device__ __forceinline__ void mma16816(float* d, const uint32_t* a, uint32_t b0, uint32_t b1) {
    asm volatile(
        "mma.sync.aligned.m16n8k16.row.col.f32.f16.f16.f32 "
        "{%0,%1,%2,%3}, {%4,%5,%6,%7}, {%8,%9}, {%0,%1,%2,%3};"
        : "+f"(d[0]), "+f"(d[1]), "+f"(d[2]), "+f"(d[3])
        : "r"(a[0]), "r"(a[1]), "r"(a[2]), "r"(a[3]), "r"(b0), "r"(b1));
}
__device__ __forceinline__ void split_h(float v, __half& h, __half& l) {
    h = __float2half_rn(v);
    l = __float2half_rn(v - __half2float(h));
}

// ===================== scratch (device globals) =============================
__device__ float g_h[cN * cHID];
__device__ __half g_h_hi[cN * cHID], g_h_lo[cN * cHID];
__device__ float g_qkv[cN * 3 * cHID];
__device__ __half g_msg_hi[cN * cHID], g_msg_lo[cN * cHID];
__device__ __half g_t1_hi[cN * cFFN], g_t1_lo[cN * cFFN];
__device__ float g_t2[cN * cHID];
__device__ float g_eA[cN * cHID], g_eB[cN * cHID];
__device__ __half g_z1_hi[(size_t)cE * cHID], g_z1_lo[(size_t)cE * cHID];
// transposed half weights: B[n][k] = W[k][n]
__device__ __half g_wqkv_hi[cL * 3 * cHID * cHID], g_wqkv_lo[cL * 3 * cHID * cHID];
__device__ __half g_wo_hi[cL * cHID * cHID],  g_wo_lo[cL * cHID * cHID];
__device__ __half g_wff1_hi[cL * cFFN * cHID], g_wff1_lo[cL * cFFN * cHID];
__device__ __half g_wff2_hi[cL * cHID * cFFN], g_wff2_lo[cL * cHID * cFFN];
__device__ __half g_weA_hi[cHID * cHID], g_weA_lo[cHID * cHID];
__device__ __half g_weB_hi[cHID * cHID], g_weB_lo[cHID * cHID];
__device__ __half g_we2_hi[96 * cHID],  g_we2_lo[96 * cHID];
// CSR
__device__ int g_deg[cN];
__device__ int g_rowptr[cN + 1];
__device__ int g_cursor[cN];
__device__ int g_csrc[cE];
__device__ int g_ceid[cE];

// ===================== CSR build ============================================
__global__ void deg_kernel(const int* __restrict__ ei) {
    int e = blockIdx.x * blockDim.x + threadIdx.x;
    if (e < cE) atomicAdd(&g_deg[ei[cE + e]], 1);
}

__global__ void scan_kernel() {
    __shared__ int sh[1024];
    __shared__ int carry;
    int tid = threadIdx.x;
    if (tid == 0) carry = 0;
    __syncthreads();
    for (int base = 0; base < cN; base += 1024) {
        int i = base + tid;
        int v = (i < cN) ? g_deg[i] : 0;
        sh[tid] = v;
        __syncthreads();
        for (int off = 1; off < 1024; off <<= 1) {
            int t = (tid >= off) ? sh[tid - off] : 0;
            __syncthreads();
            sh[tid] += t;
            __syncthreads();
        }
        if (i < cN) g_rowptr[i + 1] = carry + sh[tid];
        __syncthreads();
        if (tid == 0) carry += sh[1023];
        __syncthreads();
    }
    if (tid == 0) g_rowptr[0] = 0;
}

__global__ void fill_kernel(const int* __restrict__ ei) {
    int e = blockIdx.x * blockDim.x + threadIdx.x;
    if (e < cE) {
        int d = ei[cE + e];
        int pos = atomicAdd(&g_cursor[d], 1);
        int slot = g_rowptr[d] + pos;
        g_csrc[slot] = ei[e];
        g_ceid[slot] = e;
    }
}

// ===================== weight transpose + half split ========================
__global__ void wconv_kernel(const float* __restrict__ src, size_t src_l,
                             __half* __restrict__ dhi, __half* __restrict__ dlo,
                             size_t dst_l, int K, int N) {
    int n = blockIdx.x, l = blockIdx.y;
    const float* S = src + (size_t)l * src_l;
    __half* H = dhi + (size_t)l * dst_l + (size_t)n * K;
    __half* Lo = dlo + (size_t)l * dst_l + (size_t)n * K;
    for (int k = threadIdx.x; k < K; k += blockDim.x) {
        float v = S[(size_t)k * N + n];
        __half h, lo;
        split_h(v, h, lo);
        H[k] = h;
        Lo[k] = lo;
    }
}

// ===================== input embedding ======================================
__global__ void input_kernel(const float* __restrict__ x,
                             const int* __restrict__ batch,
                             const int* __restrict__ gptr,
                             const int* __restrict__ tg,
                             const float* __restrict__ gp,
                             const float* __restrict__ sp,
                             const float* __restrict__ ep,
                             const float* __restrict__ W,
                             const float* __restrict__ b) {
    int n = blockIdx.x;
    int j = threadIdx.x;  // 192
    __shared__ float f[16];
    __shared__ int sgid;
    if (j == 0) {
        int gid = gptr[batch[n]] + tg[n];
        gid = gid < 0 ? 0 : (gid > cG - 1 ? cG - 1 : gid);
        sgid = gid;
    }
    __syncthreads();
    if (j < 16) {
        float val;
        if (j < 4)       val = x[n * 4 + j];
        else if (j < 7)  val = gp[sgid * 3 + (j - 4)];
        else if (j < 10) val = sp[n * 3 + (j - 7)];
        else             val = ep[sgid * 6 + (j - 10)];
        f[j] = val;
    }
    __syncthreads();
    float acc = b[j];
#pragma unroll
    for (int i = 0; i < 16; i++) acc += f[i] * W[i * cHID + j];
    g_h[n * cHID + j] = acc;
    split_h(acc, g_h_hi[n * cHID + j], g_h_lo[n * cHID + j]);
}

// ===================== fp16-split HMMA GEMM ================================
// C[m, n0:n0+96] = (Ahi+Alo)(MxK) * (Bhi+Blo)^T, 3-pass fp32 accumulation.
// Tile: BM=128, BN=96, BK=64; 8 warps of 32x48; SW128 smem; cp.async 2-stage.
// MODE 0: fp32 out (+bias,+relu). MODE 1: half hi/lo out (+bias,+relu).
// MODE 2: edge-final: z2=relu(D+be2); out[m]=dot(z2,We3)+be3.
constexpr int GSTAGE = 57344;       // Ahi 16K | Alo 16K | Bhi 12K | Blo 12K
constexpr int GTAIL = 2 * GSTAGE;   // 114688
constexpr int GSMEM = GTAIL + 1280;

__device__ __forceinline__ void load_tiles(
    uint32_t s, const __half* __restrict__ Ahi, const __half* __restrict__ Alo,
    const __half* __restrict__ Bhi, const __half* __restrict__ Blo,
    int m0, int n0, int k0, int M, int K, int tid) {
#pragma unroll
    for (int q = 0; q < 4; q++) {
        int id = tid + 256 * q;
        int row = id >> 3, c16 = id & 7;
        int m = m0 + row;
        bool ok = m < M;
        size_t go = (size_t)(ok ? m : 0) * K + k0 + c16 * 8;
        uint32_t dst = s + row * 128 + ((c16 * 16) ^ ((row & 7) << 4));
        cpa16(dst, Ahi + go, ok);
        cpa16(dst + 16384, Alo + go, ok);
    }
#pragma unroll
    for (int q = 0; q < 3; q++) {
        int id = tid + 256 * q;
        int row = id >> 3, c16 = id & 7;
        size_t go = (size_t)(n0 + row) * K + k0 + c16 * 8;
        uint32_t dst = s + 32768 + row * 128 + ((c16 * 16) ^ ((row & 7) << 4));
        cpa16(dst, Bhi + go, true);
        cpa16(dst + 12288, Blo + go, true);
    }
}

__device__ __forceinline__ void compute_chunk(uint32_t s, int wm, int wn, int lane,
                                              float acc[2][6][4]) {
    int quad = lane >> 3;
    int kaddA = 16 * (quad >> 1);  // byte offset of k within row
    int kaddB = 16 * (quad & 1);
    int rowA[2], rowB[3];
#pragma unroll
    for (int i = 0; i < 2; i++) rowA[i] = 32 * wm + 16 * i + (lane & 7) + 8 * (quad & 1);
#pragma unroll
    for (int j = 0; j < 3; j++) rowB[j] = 48 * wn + 16 * j + (lane & 7) + 8 * (quad >> 1);
#pragma unroll
    for (int kk = 0; kk < 4; kk++) {
        uint32_t a[2][4], a2[2][4], b[3][4];
        int kbA = kk * 32 + kaddA;
        int kbB = kk * 32 + kaddB;
#pragma unroll
        for (int i = 0; i < 2; i++)
            ldm4(a[i], s + rowA[i] * 128 + (kbA ^ ((rowA[i] & 7) << 4)));
#pragma unroll
        for (int j = 0; j < 3; j++)
            ldm4(b[j], s + 32768 + rowB[j] * 128 + (kbB ^ ((rowB[j] & 7) << 4)));
#pragma unroll
        for (int i = 0; i < 2; i++)
#pragma unroll
            for (int j = 0; j < 6; j++)
                mma16816(acc[i][j], a[i], b[j >> 1][(j & 1) * 2], b[j >> 1][(j & 1) * 2 + 1]);
#pragma unroll
        for (int i = 0; i < 2; i++)
            ldm4(a2[i], s + 16384 + rowA[i] * 128 + (kbA ^ ((rowA[i] & 7) << 4)));
#pragma unroll
        for (int i = 0; i < 2; i++)
#pragma unroll
            for (int j = 0; j < 6; j++)
                mma16816(acc[i][j], a2[i], b[j >> 1][(j & 1) * 2], b[j >> 1][(j & 1) * 2 + 1]);
#pragma unroll
        for (int j = 0; j < 3; j++)
            ldm4(b[j], s + 45056 + rowB[j] * 128 + (kbB ^ ((rowB[j] & 7) << 4)));
#pragma unroll
        for (int i = 0; i < 2; i++)
#pragma unroll
            for (int j = 0; j < 6; j++)
                mma16816(acc[i][j], a[i], b[j >> 1][(j & 1) * 2], b[j >> 1][(j & 1) * 2 + 1]);
    }
}

template <int MODE>
__global__ __launch_bounds__(256) void gemm_mma(
    const __half* __restrict__ Ahi, const __half* __restrict__ Alo,
    const __half* __restrict__ Bhi, const __half* __restrict__ Blo,
    int M, int K, int Ntot,
    float* __restrict__ Cf, __half* __restrict__ Chi, __half* __restrict__ Clo,
    const float* __restrict__ bias, int relu,
    const float* __restrict__ We3, const float* __restrict__ be2,
    const float* __restrict__ be3, float* __restrict__ outE) {
    extern __shared__ char smem[];
    uint32_t sb = smem_to_u32(smem);
    int tid = threadIdx.x, lane = tid & 31, wid = tid >> 5;
    int wm = wid & 3, wn = wid >> 2;
    int m0 = blockIdx.x * 128, n0 = blockIdx.y * 96;
    float* tail = (float*)(smem + GTAIL);
    if (MODE == 2 && tid < 96) {
        tail[tid] = be2[tid];
        tail[96 + tid] = We3[tid];
    }
    float acc[2][6][4] = {};
    int nch = K >> 6;
    load_tiles(sb, Ahi, Alo, Bhi, Blo, m0, n0, 0, M, K, tid);
    asm volatile("cp.async.commit_group;");
    for (int c = 0; c < nch; c++) {
        if (c + 1 < nch) {
            load_tiles(sb + ((c + 1) & 1) * GSTAGE, Ahi, Alo, Bhi, Blo,
                       m0, n0, (c + 1) * 64, M, K, tid);
            asm volatile("cp.async.commit_group;");
            asm volatile("cp.async.wait_group 1;");
        } else {
            asm volatile("cp.async.wait_group 0;");
        }
        __syncthreads();
        compute_chunk(sb + (c & 1) * GSTAGE, wm, wn, lane, acc);
        __syncthreads();
    }

    if (MODE == 2) {
        float ps[2][2] = {};
#pragma unroll
        for (int i = 0; i < 2; i++)
#pragma unroll
            for (int j = 0; j < 6; j++) {
                int cl = 48 * wn + 8 * j + 2 * (lane & 3);
#pragma unroll
                for (int hh = 0; hh < 2; hh++)
#pragma unroll
                    for (int t = 0; t < 2; t++) {
                        float v = acc[i][j][2 * hh + t] + tail[cl + t];
                        v = fmaxf(v, 0.f);
                        ps[i][hh] += v * tail[96 + cl + t];
                    }
            }
#pragma unroll
        for (int i = 0; i < 2; i++)
#pragma unroll
            for (int hh = 0; hh < 2; hh++) {
                float p = ps[i][hh];
                p += __shfl_xor_sync(0xffffffffu, p, 1);
                p += __shfl_xor_sync(0xffffffffu, p, 2);
                ps[i][hh] = p;
            }
        float* rowsum = tail + 192;
        if (wn == 0 && (lane & 3) == 0) {
#pragma unroll
            for (int i = 0; i < 2; i++)
#pragma unroll
                for (int hh = 0; hh < 2; hh++)
                    rowsum[32 * wm + 16 * i + 8 * hh + (lane >> 2)] = ps[i][hh];
        }
        __syncthreads();
        if (wn == 1 && (lane & 3) == 0) {
            float b3 = __ldg(be3);
#pragma unroll
            for (int i = 0; i < 2; i++)
#pragma unroll
                for (int hh = 0; hh < 2; hh++) {
                    int r = 32 * wm + 16 * i + 8 * hh + (lane >> 2);
                    int m = m0 + r;
                    if (m < M) outE[m] = rowsum[r] + ps[i][hh] + b3;
                }
        }
    } else {
#pragma unroll
        for (int i = 0; i < 2; i++) {
            int rbase = 32 * wm + 16 * i + (lane >> 2);
#pragma unroll
            for (int hh = 0; hh < 2; hh++) {
                int m = m0 + rbase + 8 * hh;
                if (m >= M) continue;
#pragma unroll
                for (int j = 0; j < 6; j++) {
                    int col = n0 + 48 * wn + 8 * j + 2 * (lane & 3);
                    float v0 = acc[i][j][2 * hh + 0];
                    float v1 = acc[i][j][2 * hh + 1];
                    if (bias) {
                        v0 += __ldg(bias + col);
                        v1 += __ldg(bias + col + 1);
                    }
                    if (relu) {
                        v0 = fmaxf(v0, 0.f);
                        v1 = fmaxf(v1, 0.f);
                    }
                    size_t off = (size_t)m * Ntot + col;
                    if (MODE == 0) {
                        float2 f2;
                        f2.x = v0;
                        f2.y = v1;
                        *(float2*)(Cf + off) = f2;
                    } else {
                        __half h0, l0, h1, l1;
                        split_h(v0, h0, l0);
                        split_h(v1, h1, l1);
                        *(__half2*)(Chi + off) = __halves2half2(h0, h1);
                        *(__half2*)(Clo + off) = __halves2half2(l0, l1);
                    }
                }
            }
        }
    }
}

// ===================== edge-softmax attention (fp32) ========================
__global__ void attn_kernel(const float* __restrict__ ea,
                            const float* __restrict__ We) {
    int w = blockIdx.x * 8 + (threadIdx.x >> 5);
    int lane = threadIdx.x & 31;
    int n = w >> 2, h = w & 3;
    const float scale = 0.14433756729740643f;  // 1/sqrt(48)
    int qoff = n * 576 + h * cDH;
    float q0 = g_qkv[qoff + lane];
    float q1 = (lane < 16) ? g_qkv[qoff + 32 + lane] : 0.f;
    float We0[4], We1v[4];
#pragma unroll
    for (int i = 0; i < 4; i++) {
        We0[i] = We[i * cHID + h * cDH + lane];
        We1v[i] = (lane < 16) ? We[i * cHID + h * cDH + 32 + lane] : 0.f;
    }
    float m = -1e30f, den = 0.f, a0 = 0.f, a1 = 0.f;
    int beg = g_rowptr[n], end = g_rowptr[n + 1];
    for (int idx = beg; idx < end; ++idx) {
        int s = g_csrc[idx];
        int eid = g_ceid[idx];
        float ea0 = ea[eid * 4 + 0], ea1 = ea[eid * 4 + 1];
        float ea2 = ea[eid * 4 + 2], ea3 = ea[eid * 4 + 3];
        float e0 = ea0 * We0[0] + ea1 * We0[1] + ea2 * We0[2] + ea3 * We0[3];
        float e1 = ea0 * We1v[0] + ea1 * We1v[1] + ea2 * We1v[2] + ea3 * We1v[3];
        int so = s * 576 + h * cDH;
        float k0 = g_qkv[so + 192 + lane] + e0;
        float k1 = (lane < 16) ? (g_qkv[so + 224 + lane] + e1) : 0.f;
        float p = q0 * k0 + q1 * k1;
#pragma unroll
        for (int o = 16; o; o >>= 1) p += __shfl_xor_sync(0xffffffffu, p, o);
        float logit = p * scale;
        float mn = fmaxf(m, logit);
        float corr = __expf(m - mn);
        float wg = __expf(logit - mn);
        float v0 = g_qkv[so + 384 + lane] + e0;
        float v1 = (lane < 16) ? (g_qkv[so + 416 + lane] + e1) : 0.f;
        a0 = a0 * corr + wg * v0;
        a1 = a1 * corr + wg * v1;
        den = den * corr + wg;
        m = mn;
    }
    float inv = 1.f / (den + 1e-16f);
    int off = n * cHID + h * cDH;
    split_h(a0 * inv, g_msg_hi[off + lane], g_msg_lo[off + lane]);
    if (lane < 16)
        split_h(a1 * inv, g_msg_hi[off + 32 + lane], g_msg_lo[off + 32 + lane]);
}

// ===================== residual + (opt bias) + LayerNorm + half split =======
__global__ void ln_kernel(float* __restrict__ h, const float* __restrict__ add,
                          const float* __restrict__ bias,
                          const float* __restrict__ g, const float* __restrict__ b) {
    int n = blockIdx.x, j = threadIdx.x;  // 192
    __shared__ float red[192];
    __shared__ float s_mean, s_rstd;
    float v = h[n * cHID + j] + add[n * cHID + j];
    if (bias) v += bias[j];
    red[j] = v;
    __syncthreads();
    if (j < 64) red[j] += red[j + 64] + red[j + 128];
    __syncthreads();
    if (j < 32) {
        float t = red[j] + red[j + 32];
#pragma unroll
        for (int o = 16; o; o >>= 1) t += __shfl_xor_sync(0xffffffffu, t, o);
        if (j == 0) s_mean = t * (1.f / 192.f);
    }
    __syncthreads();
    float d = v - s_mean;
    red[j] = d * d;
    __syncthreads();
    if (j < 64) red[j] += red[j + 64] + red[j + 128];
    __syncthreads();
    if (j < 32) {
        float t = red[j] + red[j + 32];
#pragma unroll
        for (int o = 16; o; o >>= 1) t += __shfl_xor_sync(0xffffffffu, t, o);
        if (j == 0) s_rstd = rsqrtf(t * (1.f / 192.f) + 1e-5f);
    }
    __syncthreads();
    float outv = d * s_rstd * g[j] + b[j];
    h[n * cHID + j] = outv;
    split_h(outv, g_h_hi[n * cHID + j], g_h_lo[n * cHID + j]);
}

// ===================== z1 = relu(eA[src] + eB[dst] + ea@W_e1[384:388]) ======
__global__ __launch_bounds__(384) void z1_kernel(const float* __restrict__ ea,
                                                 const int* __restrict__ ei,
                                                 const float* __restrict__ W_e1) {
    int t = threadIdx.x;
    int sub = t >= 192 ? 1 : 0;
    int j = t - sub * 192;
    int e = blockIdx.x * 2 + sub;
    int s = ei[e], d = ei[cE + e];
    float ea0 = ea[e * 4 + 0], ea1 = ea[e * 4 + 1];
    float ea2 = ea[e * 4 + 2], ea3 = ea[e * 4 + 3];
    float v = g_eA[s * cHID + j] + g_eB[d * cHID + j]
            + ea0 * __ldg(&W_e1[384 * cHID + j]) + ea1 * __ldg(&W_e1[385 * cHID + j])
            + ea2 * __ldg(&W_e1[386 * cHID + j]) + ea3 * __ldg(&W_e1[387 * cHID + j]);
    v = fmaxf(v, 0.f);
    size_t idx = (size_t)e * cHID + j;
    split_h(v, g_z1_hi[idx], g_z1_lo[idx]);
}

// ===================== host =================================================
extern "C" void kernel_launch(void* const* d_in, const int* in_sizes, int n_in,
                              void* d_out, int out_size) {
    const float* x     = (const float*)d_in[0];
    const int*   ei    = (const int*)d_in[1];
    const float* eattr = (const float*)d_in[2];
    const int*   batch = (const int*)d_in[3];
    const int*   gptr  = (const int*)d_in[4];
    const int*   tg    = (const int*)d_in[5];
    const float* gp    = (const float*)d_in[6];
    const float* sp    = (const float*)d_in[7];
    const float* ep    = (const float*)d_in[8];
    const float* W_in  = (const float*)d_in[9];
    const float* b_in  = (const float*)d_in[10];
    const float* Wq    = (const float*)d_in[11];
    const float* Wk    = (const float*)d_in[12];
    const float* Wv    = (const float*)d_in[13];
    const float* We    = (const float*)d_in[14];
    const float* Wo    = (const float*)d_in[15];
    const float* bo    = (const float*)d_in[16];
    const float* ln1_g = (const float*)d_in[17];
    const float* ln1_b = (const float*)d_in[18];
    const float* W_ff1 = (const float*)d_in[19];
    const float* b_ff1 = (const float*)d_in[20];
    const float* W_ff2 = (const float*)d_in[21];
    const float* b_ff2 = (const float*)d_in[22];
    const float* ln2_g = (const float*)d_in[23];
    const float* ln2_b = (const float*)d_in[24];
    const float* W_e1  = (const float*)d_in[25];
    const float* b_e1  = (const float*)d_in[26];
    const float* W_e2  = (const float*)d_in[27];
    const float* b_e2  = (const float*)d_in[28];
    const float* W_e3  = (const float*)d_in[29];
    const float* b_e3  = (const float*)d_in[30];
    float* out = (float*)d_out;

    float *hb, *qkvb, *t2b, *eAb, *eBb;
    __half *h_hi, *h_lo, *msg_hi, *msg_lo, *t1_hi, *t1_lo, *z1_hi, *z1_lo;
    __half *wqkv_hi, *wqkv_lo, *wo_hi, *wo_lo, *wff1_hi, *wff1_lo, *wff2_hi, *wff2_lo;
    __half *weA_hi, *weA_lo, *weB_hi, *weB_lo, *we2_hi, *we2_lo;
    int *deg, *cursor;
    cudaGetSymbolAddress((void**)&hb, g_h);
    cudaGetSymbolAddress((void**)&qkvb, g_qkv);
    cudaGetSymbolAddress((void**)&t2b, g_t2);
    cudaGetSymbolAddress((void**)&eAb, g_eA);
    cudaGetSymbolAddress((void**)&eBb, g_eB);
    cudaGetSymbolAddress((void**)&h_hi, g_h_hi);
    cudaGetSymbolAddress((void**)&h_lo, g_h_lo);
    cudaGetSymbolAddress((void**)&msg_hi, g_msg_hi);
    cudaGetSymbolAddress((void**)&msg_lo, g_msg_lo);
    cudaGetSymbolAddress((void**)&t1_hi, g_t1_hi);
    cudaGetSymbolAddress((void**)&t1_lo, g_t1_lo);
    cudaGetSymbolAddress((void**)&z1_hi, g_z1_hi);
    cudaGetSymbolAddress((void**)&z1_lo, g_z1_lo);
    cudaGetSymbolAddress((void**)&wqkv_hi, g_wqkv_hi);
    cudaGetSymbolAddress((void**)&wqkv_lo, g_wqkv_lo);
    cudaGetSymbolAddress((void**)&wo_hi, g_wo_hi);
    cudaGetSymbolAddress((void**)&wo_lo, g_wo_lo);
    cudaGetSymbolAddress((void**)&wff1_hi, g_wff1_hi);
    cudaGetSymbolAddress((void**)&wff1_lo, g_wff1_lo);
    cudaGetSymbolAddress((void**)&wff2_hi, g_wff2_hi);
    cudaGetSymbolAddress((void**)&wff2_lo, g_wff2_lo);
    cudaGetSymbolAddress((void**)&weA_hi, g_weA_hi);
    cudaGetSymbolAddress((void**)&weA_lo, g_weA_lo);
    cudaGetSymbolAddress((void**)&weB_hi, g_weB_hi);
    cudaGetSymbolAddress((void**)&weB_lo, g_weB_lo);
    cudaGetSymbolAddress((void**)&we2_hi, g_we2_hi);
    cudaGetSymbolAddress((void**)&we2_lo, g_we2_lo);
    cudaGetSymbolAddress((void**)&deg, g_deg);
    cudaGetSymbolAddress((void**)&cursor, g_cursor);

    cudaFuncSetAttribute(gemm_mma<0>, cudaFuncAttributeMaxDynamicSharedMemorySize, GSMEM);
    cudaFuncSetAttribute(gemm_mma<1>, cudaFuncAttributeMaxDynamicSharedMemorySize, GSMEM);
    cudaFuncSetAttribute(gemm_mma<2>, cudaFuncAttributeMaxDynamicSharedMemorySize, GSMEM);

    const int MB = (cN + 127) / 128;  // 313

    // CSR over dst
    cudaMemsetAsync(deg, 0, cN * sizeof(int));
    cudaMemsetAsync(cursor, 0, cN * sizeof(int));
    deg_kernel<<<(cE + 255) / 256, 256>>>(ei);
    scan_kernel<<<1, 1024>>>();
    fill_kernel<<<(cE + 255) / 256, 256>>>(ei);

    // weight transpose + half split
    wconv_kernel<<<dim3(192, 3), 128>>>(Wq, (size_t)192 * 192, wqkv_hi, wqkv_lo, (size_t)576 * 192, 192, 192);
    wconv_kernel<<<dim3(192, 3), 128>>>(Wk, (size_t)192 * 192, wqkv_hi + 192 * 192, wqkv_lo + 192 * 192, (size_t)576 * 192, 192, 192);
    wconv_kernel<<<dim3(192, 3), 128>>>(Wv, (size_t)192 * 192, wqkv_hi + 384 * 192, wqkv_lo + 384 * 192, (size_t)576 * 192, 192, 192);
    wconv_kernel<<<dim3(192, 3), 128>>>(Wo, (size_t)192 * 192, wo_hi, wo_lo, (size_t)192 * 192, 192, 192);
    wconv_kernel<<<dim3(384, 3), 128>>>(W_ff1, (size_t)192 * 384, wff1_hi, wff1_lo, (size_t)384 * 192, 192, 384);
    wconv_kernel<<<dim3(192, 3), 128>>>(W_ff2, (size_t)384 * 192, wff2_hi, wff2_lo, (size_t)192 * 384, 384, 192);
    wconv_kernel<<<dim3(192, 1), 128>>>(W_e1, 0, weA_hi, weA_lo, 0, 192, 192);
    wconv_kernel<<<dim3(192, 1), 128>>>(W_e1 + 192 * 192, 0, weB_hi, weB_lo, 0, 192, 192);
    wconv_kernel<<<dim3(96, 1), 128>>>(W_e2, 0, we2_hi, we2_lo, 0, 192, 96);

    // input embedding
    input_kernel<<<cN, 192>>>(x, batch, gptr, tg, gp, sp, ep, W_in, b_in);

    for (int l = 0; l < cL; l++) {
        // QKV fused: C[N,576] fp32
        gemm_mma<0><<<dim3(MB, 6), 256, GSMEM>>>(
            h_hi, h_lo, wqkv_hi + (size_t)l * 576 * 192, wqkv_lo + (size_t)l * 576 * 192,
            cN, 192, 576, qkvb, nullptr, nullptr, nullptr, 0,
            nullptr, nullptr, nullptr, nullptr);
        attn_kernel<<<cN * cHEADS / 8, 256>>>(eattr, We + l * 4 * cHID);
        // O projection from msg (half split)
        gemm_mma<0><<<dim3(MB, 2), 256, GSMEM>>>(
            msg_hi, msg_lo, wo_hi + (size_t)l * 192 * 192, wo_lo + (size_t)l * 192 * 192,
            cN, 192, 192, t2b, nullptr, nullptr, nullptr, 0,
            nullptr, nullptr, nullptr, nullptr);
        ln_kernel<<<cN, 192>>>(hb, t2b, bo + l * cHID, ln1_g + l * cHID, ln1_b + l * cHID);
        // FF1: relu(h@W1+b1) -> half split t1
        gemm_mma<1><<<dim3(MB, 4), 256, GSMEM>>>(
            h_hi, h_lo, wff1_hi + (size_t)l * 384 * 192, wff1_lo + (size_t)l * 384 * 192,
            cN, 192, 384, nullptr, t1_hi, t1_lo, b_ff1 + l * cFFN, 1,
            nullptr, nullptr, nullptr, nullptr);
        // FF2: t1@W2 + b2 -> fp32 t2
        gemm_mma<0><<<dim3(MB, 2), 256, GSMEM>>>(
            t1_hi, t1_lo, wff2_hi + (size_t)l * 192 * 384, wff2_lo + (size_t)l * 192 * 384,
            cN, 384, 192, t2b, nullptr, nullptr, b_ff2 + l * cHID, 0,
            nullptr, nullptr, nullptr, nullptr);
        ln_kernel<<<cN, 192>>>(hb, t2b, nullptr, ln2_g + l * cHID, ln2_b + l * cHID);
    }

    // edge head node GEMMs: eA = h@W_e1[0:192]+b_e1 ; eB = h@W_e1[192:384]
    gemm_mma<0><<<dim3(MB, 2), 256, GSMEM>>>(
        h_hi, h_lo, weA_hi, weA_lo, cN, 192, 192, eAb, nullptr, nullptr, b_e1, 0,
        nullptr, nullptr, nullptr, nullptr);
    gemm_mma<0><<<dim3(MB, 2), 256, GSMEM>>>(
        h_hi, h_lo, weB_hi, weB_lo, cN, 192, 192, eBb, nullptr, nullptr, nullptr, 0,
        nullptr, nullptr, nullptr, nullptr);
    // per-edge z1 (half split)
    z1_kernel<<<cE / 2, 384>>>(eattr, ei, W_e1);
    // edge GEMM + fused relu/W_e3 reduction -> out[E]
    gemm_mma<2><<<dim3(cE / 128, 1), 256, GSMEM>>>(
        z1_hi, z1_lo, we2_hi, we2_lo, cE, 192, 96, nullptr, nullptr, nullptr, nullptr, 0,
        W_e3, b_e2, b_e3, out);
}

// round 6
// speedup vs baseline: 1.9905x; 1.0120x over previous
#include <cuda_runtime.h>
#include <cuda_fp16.h>
#include <cstdint>
#include <math.h>

// Problem constants
constexpr int cN = 40000, cE = 400000, cG = 512;
constexpr int cHID = 192, cHEADS = 4, cDH = 48, cFFN = 384, cL = 3;

__device__ __forceinline__ uint32_t smem_to_u32(const void* p) {
    uint32_t a;
    asm("{ .reg .u64 t; cvta.to.shared.u64 t, %1; cvt.u32.u64 %0, t; }" : "=r"(a) : "l"(p));
    return a;
}
__device__ __forceinline__ void cpa16(uint32_t dst, const void* src, bool v) {
    int sz = v ? 16 : 0;
    asm volatile("cp.async.cg.shared.global [%0], [%1], 16, %2;"
                 :: "r"(dst), "l"(src), "r"(sz));
}
__device__ __forceinline__ void ldm4(uint32_t* r, uint32_t a) {
    asm volatile("ldmatrix.sync.aligned.m8n8.x4.shared.b16 {%0,%1,%2,%3}, [%4];"
        : "=r"(r[0]), "=r"(r[1]), "=r"(r[2]), "=r"(r[3]) : "r"(a));
}
__device__ __forceinline__ void mma16816(float* d, const uint32_t* a, uint32_t b0, uint32_t b1) {
    asm volatile(
        "mma.sync.aligned.m16n8k16.row.col.f32.f16.f16.f32 "
        "{%0,%1,%2,%3}, {%4,%5,%6,%7}, {%8,%9}, {%0,%1,%2,%3};"
        : "+f"(d[0]), "+f"(d[1]), "+f"(d[2]), "+f"(d[3])
        : "r"(a[0]), "r"(a[1]), "r"(a[2]), "r"(a[3]), "r"(b0), "r"(b1));
}
__device__ __forceinline__ void split_h(float v, __half& h, __half& l) {
    h = __float2half_rn(v);
    l = __float2half_rn(v - __half2float(h));
}

// ===================== scratch (device globals) =============================
__device__ float g_h[cN * cHID];
__device__ __half g_h_hi[cN * cHID], g_h_lo[cN * cHID];
__device__ float g_qkv[cN * 3 * cHID];
__device__ __half g_msg_hi[cN * cHID], g_msg_lo[cN * cHID];
__device__ __half g_t1_hi[cN * cFFN], g_t1_lo[cN * cFFN];
__device__ float g_t2[cN * cHID];
__device__ float g_eA[cN * cHID], g_eB[cN * cHID];
__device__ __half g_z1_hi[(size_t)cE * cHID], g_z1_lo[(size_t)cE * cHID];
// transposed half weights: B[n][k] = W[k][n]
__device__ __half g_wqkv_hi[cL * 3 * cHID * cHID], g_wqkv_lo[cL * 3 * cHID * cHID];
__device__ __half g_wo_hi[cL * cHID * cHID],  g_wo_lo[cL * cHID * cHID];
__device__ __half g_wff1_hi[cL * cFFN * cHID], g_wff1_lo[cL * cFFN * cHID];
__device__ __half g_wff2_hi[cL * cHID * cFFN], g_wff2_lo[cL * cHID * cFFN];
__device__ __half g_weA_hi[cHID * cHID], g_weA_lo[cHID * cHID];
__device__ __half g_weB_hi[cHID * cHID], g_weB_lo[cHID * cHID];
__device__ __half g_we2_hi[96 * cHID],  g_we2_lo[96 * cHID];
// CSR
__device__ int g_deg[cN];
__device__ int g_rowptr[cN + 1];
__device__ int g_cursor[cN];
__device__ int g_csrc[cE];
__device__ int g_ceid[cE];

// ===================== CSR build ============================================
__global__ void deg_kernel(const int* __restrict__ ei) {
    int e = blockIdx.x * blockDim.x + threadIdx.x;
    if (e < cE) atomicAdd(&g_deg[ei[cE + e]], 1);
}

__global__ void scan_kernel() {
    __shared__ int sh[1024];
    __shared__ int carry;
    int tid = threadIdx.x;
    if (tid == 0) carry = 0;
    __syncthreads();
    for (int base = 0; base < cN; base += 1024) {
        int i = base + tid;
        int v = (i < cN) ? g_deg[i] : 0;
        sh[tid] = v;
        __syncthreads();
        for (int off = 1; off < 1024; off <<= 1) {
            int t = (tid >= off) ? sh[tid - off] : 0;
            __syncthreads();
            sh[tid] += t;
            __syncthreads();
        }
        if (i < cN) g_rowptr[i + 1] = carry + sh[tid];
        __syncthreads();
        if (tid == 0) carry += sh[1023];
        __syncthreads();
    }
    if (tid == 0) g_rowptr[0] = 0;
}

__global__ void fill_kernel(const int* __restrict__ ei) {
    int e = blockIdx.x * blockDim.x + threadIdx.x;
    if (e < cE) {
        int d = ei[cE + e];
        int pos = atomicAdd(&g_cursor[d], 1);
        int slot = g_rowptr[d] + pos;
        g_csrc[slot] = ei[e];
        g_ceid[slot] = e;
    }
}

// ===================== weight transpose + half split ========================
__global__ void wconv_kernel(const float* __restrict__ src, size_t src_l,
                             __half* __restrict__ dhi, __half* __restrict__ dlo,
                             size_t dst_l, int K, int N) {
    int n = blockIdx.x, l = blockIdx.y;
    const float* S = src + (size_t)l * src_l;
    __half* H = dhi + (size_t)l * dst_l + (size_t)n * K;
    __half* Lo = dlo + (size_t)l * dst_l + (size_t)n * K;
    for (int k = threadIdx.x; k < K; k += blockDim.x) {
        float v = S[(size_t)k * N + n];
        __half h, lo;
        split_h(v, h, lo);
        H[k] = h;
        Lo[k] = lo;
    }
}

// ===================== input embedding ======================================
__global__ void input_kernel(const float* __restrict__ x,
                             const int* __restrict__ batch,
                             const int* __restrict__ gptr,
                             const int* __restrict__ tg,
                             const float* __restrict__ gp,
                             const float* __restrict__ sp,
                             const float* __restrict__ ep,
                             const float* __restrict__ W,
                             const float* __restrict__ b) {
    int n = blockIdx.x;
    int j = threadIdx.x;  // 192
    __shared__ float f[16];
    __shared__ int sgid;
    if (j == 0) {
        int gid = gptr[batch[n]] + tg[n];
        gid = gid < 0 ? 0 : (gid > cG - 1 ? cG - 1 : gid);
        sgid = gid;
    }
    __syncthreads();
    if (j < 16) {
        float val;
        if (j < 4)       val = x[n * 4 + j];
        else if (j < 7)  val = gp[sgid * 3 + (j - 4)];
        else if (j < 10) val = sp[n * 3 + (j - 7)];
        else             val = ep[sgid * 6 + (j - 10)];
        f[j] = val;
    }
    __syncthreads();
    float acc = b[j];
#pragma unroll
    for (int i = 0; i < 16; i++) acc += f[i] * W[i * cHID + j];
    g_h[n * cHID + j] = acc;
    split_h(acc, g_h_hi[n * cHID + j], g_h_lo[n * cHID + j]);
}

// ===================== fp16-split HMMA GEMM ================================
// C[m, n0:n0+96] = (Ahi+Alo)(MxK) * (Bhi+Blo)^T, 3-pass fp32 accumulation.
// Tile: BM=128, BN=96, BK=64; 8 warps of 32x48; SW128 smem; cp.async 2-stage.
// MODE 0: fp32 out (+bias,+relu). MODE 1: half hi/lo out (+bias,+relu).
// MODE 2: edge-final: z2=relu(D+be2); out[m]=dot(z2,We3)+be3.
constexpr int GSTAGE = 57344;       // Ahi 16K | Alo 16K | Bhi 12K | Blo 12K
constexpr int GTAIL = 2 * GSTAGE;   // 114688
constexpr int GSMEM = GTAIL + 1280;

__device__ __forceinline__ void load_tiles(
    uint32_t s, const __half* __restrict__ Ahi, const __half* __restrict__ Alo,
    const __half* __restrict__ Bhi, const __half* __restrict__ Blo,
    int m0, int n0, int k0, int M, int K, int tid) {
#pragma unroll
    for (int q = 0; q < 4; q++) {
        int id = tid + 256 * q;
        int row = id >> 3, c16 = id & 7;
        int m = m0 + row;
        bool ok = m < M;
        size_t go = (size_t)(ok ? m : 0) * K + k0 + c16 * 8;
        uint32_t dst = s + row * 128 + ((c16 * 16) ^ ((row & 7) << 4));
        cpa16(dst, Ahi + go, ok);
        cpa16(dst + 16384, Alo + go, ok);
    }
#pragma unroll
    for (int q = 0; q < 3; q++) {
        int id = tid + 256 * q;
        int row = id >> 3, c16 = id & 7;
        size_t go = (size_t)(n0 + row) * K + k0 + c16 * 8;
        uint32_t dst = s + 32768 + row * 128 + ((c16 * 16) ^ ((row & 7) << 4));
        cpa16(dst, Bhi + go, true);
        cpa16(dst + 12288, Blo + go, true);
    }
}

__device__ __forceinline__ void compute_chunk(uint32_t s, int wm, int wn, int lane,
                                              float acc[2][6][4]) {
    int quad = lane >> 3;
    int kaddA = 16 * (quad >> 1);  // byte offset of k within row
    int kaddB = 16 * (quad & 1);
    int rowA[2], rowB[3];
#pragma unroll
    for (int i = 0; i < 2; i++) rowA[i] = 32 * wm + 16 * i + (lane & 7) + 8 * (quad & 1);
#pragma unroll
    for (int j = 0; j < 3; j++) rowB[j] = 48 * wn + 16 * j + (lane & 7) + 8 * (quad >> 1);
#pragma unroll
    for (int kk = 0; kk < 4; kk++) {
        uint32_t a[2][4], a2[2][4], b[3][4];
        int kbA = kk * 32 + kaddA;
        int kbB = kk * 32 + kaddB;
#pragma unroll
        for (int i = 0; i < 2; i++)
            ldm4(a[i], s + rowA[i] * 128 + (kbA ^ ((rowA[i] & 7) << 4)));
#pragma unroll
        for (int j = 0; j < 3; j++)
            ldm4(b[j], s + 32768 + rowB[j] * 128 + (kbB ^ ((rowB[j] & 7) << 4)));
#pragma unroll
        for (int i = 0; i < 2; i++)
#pragma unroll
            for (int j = 0; j < 6; j++)
                mma16816(acc[i][j], a[i], b[j >> 1][(j & 1) * 2], b[j >> 1][(j & 1) * 2 + 1]);
#pragma unroll
        for (int i = 0; i < 2; i++)
            ldm4(a2[i], s + 16384 + rowA[i] * 128 + (kbA ^ ((rowA[i] & 7) << 4)));
#pragma unroll
        for (int i = 0; i < 2; i++)
#pragma unroll
            for (int j = 0; j < 6; j++)
                mma16816(acc[i][j], a2[i], b[j >> 1][(j & 1) * 2], b[j >> 1][(j & 1) * 2 + 1]);
#pragma unroll
        for (int j = 0; j < 3; j++)
            ldm4(b[j], s + 45056 + rowB[j] * 128 + (kbB ^ ((rowB[j] & 7) << 4)));
#pragma unroll
        for (int i = 0; i < 2; i++)
#pragma unroll
            for (int j = 0; j < 6; j++)
                mma16816(acc[i][j], a[i], b[j >> 1][(j & 1) * 2], b[j >> 1][(j & 1) * 2 + 1]);
    }
}

template <int MODE>
__global__ __launch_bounds__(256) void gemm_mma(
    const __half* __restrict__ Ahi, const __half* __restrict__ Alo,
    const __half* __restrict__ Bhi, const __half* __restrict__ Blo,
    int M, int K, int Ntot,
    float* __restrict__ Cf, __half* __restrict__ Chi, __half* __restrict__ Clo,
    const float* __restrict__ bias, int relu,
    const float* __restrict__ We3, const float* __restrict__ be2,
    const float* __restrict__ be3, float* __restrict__ outE) {
    extern __shared__ char smem[];
    uint32_t sb = smem_to_u32(smem);
    int tid = threadIdx.x, lane = tid & 31, wid = tid >> 5;
    int wm = wid & 3, wn = wid >> 2;
    int m0 = blockIdx.x * 128, n0 = blockIdx.y * 96;
    float* tail = (float*)(smem + GTAIL);
    if (MODE == 2 && tid < 96) {
        tail[tid] = be2[tid];
        tail[96 + tid] = We3[tid];
    }
    float acc[2][6][4] = {};
    int nch = K >> 6;
    load_tiles(sb, Ahi, Alo, Bhi, Blo, m0, n0, 0, M, K, tid);
    asm volatile("cp.async.commit_group;");
    for (int c = 0; c < nch; c++) {
        if (c + 1 < nch) {
            load_tiles(sb + ((c + 1) & 1) * GSTAGE, Ahi, Alo, Bhi, Blo,
                       m0, n0, (c + 1) * 64, M, K, tid);
            asm volatile("cp.async.commit_group;");
            asm volatile("cp.async.wait_group 1;");
        } else {
            asm volatile("cp.async.wait_group 0;");
        }
        __syncthreads();
        compute_chunk(sb + (c & 1) * GSTAGE, wm, wn, lane, acc);
        __syncthreads();
    }

    if (MODE == 2) {
        float ps[2][2] = {};
#pragma unroll
        for (int i = 0; i < 2; i++)
#pragma unroll
            for (int j = 0; j < 6; j++) {
                int cl = 48 * wn + 8 * j + 2 * (lane & 3);
#pragma unroll
                for (int hh = 0; hh < 2; hh++)
#pragma unroll
                    for (int t = 0; t < 2; t++) {
                        float v = acc[i][j][2 * hh + t] + tail[cl + t];
                        v = fmaxf(v, 0.f);
                        ps[i][hh] += v * tail[96 + cl + t];
                    }
            }
#pragma unroll
        for (int i = 0; i < 2; i++)
#pragma unroll
            for (int hh = 0; hh < 2; hh++) {
                float p = ps[i][hh];
                p += __shfl_xor_sync(0xffffffffu, p, 1);
                p += __shfl_xor_sync(0xffffffffu, p, 2);
                ps[i][hh] = p;
            }
        float* rowsum = tail + 192;
        if (wn == 0 && (lane & 3) == 0) {
#pragma unroll
            for (int i = 0; i < 2; i++)
#pragma unroll
                for (int hh = 0; hh < 2; hh++)
                    rowsum[32 * wm + 16 * i + 8 * hh + (lane >> 2)] = ps[i][hh];
        }
        __syncthreads();
        if (wn == 1 && (lane & 3) == 0) {
            float b3 = __ldg(be3);
#pragma unroll
            for (int i = 0; i < 2; i++)
#pragma unroll
                for (int hh = 0; hh < 2; hh++) {
                    int r = 32 * wm + 16 * i + 8 * hh + (lane >> 2);
                    int m = m0 + r;
                    if (m < M) outE[m] = rowsum[r] + ps[i][hh] + b3;
                }
        }
    } else {
#pragma unroll
        for (int i = 0; i < 2; i++) {
            int rbase = 32 * wm + 16 * i + (lane >> 2);
#pragma unroll
            for (int hh = 0; hh < 2; hh++) {
                int m = m0 + rbase + 8 * hh;
                if (m >= M) continue;
#pragma unroll
                for (int j = 0; j < 6; j++) {
                    int col = n0 + 48 * wn + 8 * j + 2 * (lane & 3);
                    float v0 = acc[i][j][2 * hh + 0];
                    float v1 = acc[i][j][2 * hh + 1];
                    if (bias) {
                        v0 += __ldg(bias + col);
                        v1 += __ldg(bias + col + 1);
                    }
                    if (relu) {
                        v0 = fmaxf(v0, 0.f);
                        v1 = fmaxf(v1, 0.f);
                    }
                    size_t off = (size_t)m * Ntot + col;
                    if (MODE == 0) {
                        float2 f2;
                        f2.x = v0;
                        f2.y = v1;
                        *(float2*)(Cf + off) = f2;
                    } else {
                        __half h0, l0, h1, l1;
                        split_h(v0, h0, l0);
                        split_h(v1, h1, l1);
                        *(__half2*)(Chi + off) = __halves2half2(h0, h1);
                        *(__half2*)(Clo + off) = __halves2half2(l0, l1);
                    }
                }
            }
        }
    }
}

// ===================== edge-softmax attention (fp32) ========================
__global__ void attn_kernel(const float* __restrict__ ea,
                            const float* __restrict__ We) {
    int w = blockIdx.x * 8 + (threadIdx.x >> 5);
    int lane = threadIdx.x & 31;
    int n = w >> 2, h = w & 3;
    const float scale = 0.14433756729740643f;  // 1/sqrt(48)
    int qoff = n * 576 + h * cDH;
    float q0 = g_qkv[qoff + lane];
    float q1 = (lane < 16) ? g_qkv[qoff + 32 + lane] : 0.f;
    float We0[4], We1v[4];
#pragma unroll
    for (int i = 0; i < 4; i++) {
        We0[i] = We[i * cHID + h * cDH + lane];
        We1v[i] = (lane < 16) ? We[i * cHID + h * cDH + 32 + lane] : 0.f;
    }
    float m = -1e30f, den = 0.f, a0 = 0.f, a1 = 0.f;
    int beg = g_rowptr[n], end = g_rowptr[n + 1];
    for (int idx = beg; idx < end; ++idx) {
        int s = g_csrc[idx];
        int eid = g_ceid[idx];
        float ea0 = ea[eid * 4 + 0], ea1 = ea[eid * 4 + 1];
        float ea2 = ea[eid * 4 + 2], ea3 = ea[eid * 4 + 3];
        float e0 = ea0 * We0[0] + ea1 * We0[1] + ea2 * We0[2] + ea3 * We0[3];
        float e1 = ea0 * We1v[0] + ea1 * We1v[1] + ea2 * We1v[2] + ea3 * We1v[3];
        int so = s * 576 + h * cDH;
        float k0 = g_qkv[so + 192 + lane] + e0;
        float k1 = (lane < 16) ? (g_qkv[so + 224 + lane] + e1) : 0.f;
        float p = q0 * k0 + q1 * k1;
#pragma unroll
        for (int o = 16; o; o >>= 1) p += __shfl_xor_sync(0xffffffffu, p, o);
        float logit = p * scale;
        float mn = fmaxf(m, logit);
        float corr = __expf(m - mn);
        float wg = __expf(logit - mn);
        float v0 = g_qkv[so + 384 + lane] + e0;
        float v1 = (lane < 16) ? (g_qkv[so + 416 + lane] + e1) : 0.f;
        a0 = a0 * corr + wg * v0;
        a1 = a1 * corr + wg * v1;
        den = den * corr + wg;
        m = mn;
    }
    float inv = 1.f / (den + 1e-16f);
    int off = n * cHID + h * cDH;
    split_h(a0 * inv, g_msg_hi[off + lane], g_msg_lo[off + lane]);
    if (lane < 16)
        split_h(a1 * inv, g_msg_hi[off + 32 + lane], g_msg_lo[off + 32 + lane]);
}

// ===================== residual + (opt bias) + LayerNorm + half split =======
__global__ void ln_kernel(float* __restrict__ h, const float* __restrict__ add,
                          const float* __restrict__ bias,
                          const float* __restrict__ g, const float* __restrict__ b) {
    int n = blockIdx.x, j = threadIdx.x;  // 192
    __shared__ float red[192];
    __shared__ float s_mean, s_rstd;
    float v = h[n * cHID + j] + add[n * cHID + j];
    if (bias) v += bias[j];
    red[j] = v;
    __syncthreads();
    if (j < 64) red[j] += red[j + 64] + red[j + 128];
    __syncthreads();
    if (j < 32) {
        float t = red[j] + red[j + 32];
#pragma unroll
        for (int o = 16; o; o >>= 1) t += __shfl_xor_sync(0xffffffffu, t, o);
        if (j == 0) s_mean = t * (1.f / 192.f);
    }
    __syncthreads();
    float d = v - s_mean;
    red[j] = d * d;
    __syncthreads();
    if (j < 64) red[j] += red[j + 64] + red[j + 128];
    __syncthreads();
    if (j < 32) {
        float t = red[j] + red[j + 32];
#pragma unroll
        for (int o = 16; o; o >>= 1) t += __shfl_xor_sync(0xffffffffu, t, o);
        if (j == 0) s_rstd = rsqrtf(t * (1.f / 192.f) + 1e-5f);
    }
    __syncthreads();
    float outv = d * s_rstd * g[j] + b[j];
    h[n * cHID + j] = outv;
    split_h(outv, g_h_hi[n * cHID + j], g_h_lo[n * cHID + j]);
}

// ===================== z1 = relu(eA[src] + eB[dst] + ea@W_e1[384:388]) ======
__global__ __launch_bounds__(384) void z1_kernel(const float* __restrict__ ea,
                                                 const int* __restrict__ ei,
                                                 const float* __restrict__ W_e1) {
    int t = threadIdx.x;
    int sub = t >= 192 ? 1 : 0;
    int j = t - sub * 192;
    int e = blockIdx.x * 2 + sub;
    int s = ei[e], d = ei[cE + e];
    float ea0 = ea[e * 4 + 0], ea1 = ea[e * 4 + 1];
    float ea2 = ea[e * 4 + 2], ea3 = ea[e * 4 + 3];
    float v = g_eA[s * cHID + j] + g_eB[d * cHID + j]
            + ea0 * __ldg(&W_e1[384 * cHID + j]) + ea1 * __ldg(&W_e1[385 * cHID + j])
            + ea2 * __ldg(&W_e1[386 * cHID + j]) + ea3 * __ldg(&W_e1[387 * cHID + j]);
    v = fmaxf(v, 0.f);
    size_t idx = (size_t)e * cHID + j;
    split_h(v, g_z1_hi[idx], g_z1_lo[idx]);
}

// ===================== host =================================================
extern "C" void kernel_launch(void* const* d_in, const int* in_sizes, int n_in,
                              void* d_out, int out_size) {
    const float* x     = (const float*)d_in[0];
    const int*   ei    = (const int*)d_in[1];
    const float* eattr = (const float*)d_in[2];
    const int*   batch = (const int*)d_in[3];
    const int*   gptr  = (const int*)d_in[4];
    const int*   tg    = (const int*)d_in[5];
    const float* gp    = (const float*)d_in[6];
    const float* sp    = (const float*)d_in[7];
    const float* ep    = (const float*)d_in[8];
    const float* W_in  = (const float*)d_in[9];
    const float* b_in  = (const float*)d_in[10];
    const float* Wq    = (const float*)d_in[11];
    const float* Wk    = (const float*)d_in[12];
    const float* Wv    = (const float*)d_in[13];
    const float* We    = (const float*)d_in[14];
    const float* Wo    = (const float*)d_in[15];
    const float* bo    = (const float*)d_in[16];
    const float* ln1_g = (const float*)d_in[17];
    const float* ln1_b = (const float*)d_in[18];
    const float* W_ff1 = (const float*)d_in[19];
    const float* b_ff1 = (const float*)d_in[20];
    const float* W_ff2 = (const float*)d_in[21];
    const float* b_ff2 = (const float*)d_in[22];
    const float* ln2_g = (const float*)d_in[23];
    const float* ln2_b = (const float*)d_in[24];
    const float* W_e1  = (const float*)d_in[25];
    const float* b_e1  = (const float*)d_in[26];
    const float* W_e2  = (const float*)d_in[27];
    const float* b_e2  = (const float*)d_in[28];
    const float* W_e3  = (const float*)d_in[29];
    const float* b_e3  = (const float*)d_in[30];
    float* out = (float*)d_out;

    float *hb, *qkvb, *t2b, *eAb, *eBb;
    __half *h_hi, *h_lo, *msg_hi, *msg_lo, *t1_hi, *t1_lo, *z1_hi, *z1_lo;
    __half *wqkv_hi, *wqkv_lo, *wo_hi, *wo_lo, *wff1_hi, *wff1_lo, *wff2_hi, *wff2_lo;
    __half *weA_hi, *weA_lo, *weB_hi, *weB_lo, *we2_hi, *we2_lo;
    int *deg, *cursor;
    cudaGetSymbolAddress((void**)&hb, g_h);
    cudaGetSymbolAddress((void**)&qkvb, g_qkv);
    cudaGetSymbolAddress((void**)&t2b, g_t2);
    cudaGetSymbolAddress((void**)&eAb, g_eA);
    cudaGetSymbolAddress((void**)&eBb, g_eB);
    cudaGetSymbolAddress((void**)&h_hi, g_h_hi);
    cudaGetSymbolAddress((void**)&h_lo, g_h_lo);
    cudaGetSymbolAddress((void**)&msg_hi, g_msg_hi);
    cudaGetSymbolAddress((void**)&msg_lo, g_msg_lo);
    cudaGetSymbolAddress((void**)&t1_hi, g_t1_hi);
    cudaGetSymbolAddress((void**)&t1_lo, g_t1_lo);
    cudaGetSymbolAddress((void**)&z1_hi, g_z1_hi);
    cudaGetSymbolAddress((void**)&z1_lo, g_z1_lo);
    cudaGetSymbolAddress((void**)&wqkv_hi, g_wqkv_hi);
    cudaGetSymbolAddress((void**)&wqkv_lo, g_wqkv_lo);
    cudaGetSymbolAddress((void**)&wo_hi, g_wo_hi);
    cudaGetSymbolAddress((void**)&wo_lo, g_wo_lo);
    cudaGetSymbolAddress((void**)&wff1_hi, g_wff1_hi);
    cudaGetSymbolAddress((void**)&wff1_lo, g_wff1_lo);
    cudaGetSymbolAddress((void**)&wff2_hi, g_wff2_hi);
    cudaGetSymbolAddress((void**)&wff2_lo, g_wff2_lo);
    cudaGetSymbolAddress((void**)&weA_hi, g_weA_hi);
    cudaGetSymbolAddress((void**)&weA_lo, g_weA_lo);
    cudaGetSymbolAddress((void**)&weB_hi, g_weB_hi);
    cudaGetSymbolAddress((void**)&weB_lo, g_weB_lo);
    cudaGetSymbolAddress((void**)&we2_hi, g_we2_hi);
    cudaGetSymbolAddress((void**)&we2_lo, g_we2_lo);
    cudaGetSymbolAddress((void**)&deg, g_deg);
    cudaGetSymbolAddress((void**)&cursor, g_cursor);

    cudaFuncSetAttribute(gemm_mma<0>, cudaFuncAttributeMaxDynamicSharedMemorySize, GSMEM);
    cudaFuncSetAttribute(gemm_mma<1>, cudaFuncAttributeMaxDynamicSharedMemorySize, GSMEM);
    cudaFuncSetAttribute(gemm_mma<2>, cudaFuncAttributeMaxDynamicSharedMemorySize, GSMEM);

    const int MB = (cN + 127) / 128;  // 313

    // CSR over dst
    cudaMemsetAsync(deg, 0, cN * sizeof(int));
    cudaMemsetAsync(cursor, 0, cN * sizeof(int));
    deg_kernel<<<(cE + 255) / 256, 256>>>(ei);
    scan_kernel<<<1, 1024>>>();
    fill_kernel<<<(cE + 255) / 256, 256>>>(ei);

    // weight transpose + half split
    wconv_kernel<<<dim3(192, 3), 128>>>(Wq, (size_t)192 * 192, wqkv_hi, wqkv_lo, (size_t)576 * 192, 192, 192);
    wconv_kernel<<<dim3(192, 3), 128>>>(Wk, (size_t)192 * 192, wqkv_hi + 192 * 192, wqkv_lo + 192 * 192, (size_t)576 * 192, 192, 192);
    wconv_kernel<<<dim3(192, 3), 128>>>(Wv, (size_t)192 * 192, wqkv_hi + 384 * 192, wqkv_lo + 384 * 192, (size_t)576 * 192, 192, 192);
    wconv_kernel<<<dim3(192, 3), 128>>>(Wo, (size_t)192 * 192, wo_hi, wo_lo, (size_t)192 * 192, 192, 192);
    wconv_kernel<<<dim3(384, 3), 128>>>(W_ff1, (size_t)192 * 384, wff1_hi, wff1_lo, (size_t)384 * 192, 192, 384);
    wconv_kernel<<<dim3(192, 3), 128>>>(W_ff2, (size_t)384 * 192, wff2_hi, wff2_lo, (size_t)192 * 384, 384, 192);
    wconv_kernel<<<dim3(192, 1), 128>>>(W_e1, 0, weA_hi, weA_lo, 0, 192, 192);
    wconv_kernel<<<dim3(192, 1), 128>>>(W_e1 + 192 * 192, 0, weB_hi, weB_lo, 0, 192, 192);
    wconv_kernel<<<dim3(96, 1), 128>>>(W_e2, 0, we2_hi, we2_lo, 0, 192, 96);

    // input embedding
    input_kernel<<<cN, 192>>>(x, batch, gptr, tg, gp, sp, ep, W_in, b_in);

    for (int l = 0; l < cL; l++) {
        // QKV fused: C[N,576] fp32
        gemm_mma<0><<<dim3(MB, 6), 256, GSMEM>>>(
            h_hi, h_lo, wqkv_hi + (size_t)l * 576 * 192, wqkv_lo + (size_t)l * 576 * 192,
            cN, 192, 576, qkvb, nullptr, nullptr, nullptr, 0,
            nullptr, nullptr, nullptr, nullptr);
        attn_kernel<<<cN * cHEADS / 8, 256>>>(eattr, We + l * 4 * cHID);
        // O projection from msg (half split)
        gemm_mma<0><<<dim3(MB, 2), 256, GSMEM>>>(
            msg_hi, msg_lo, wo_hi + (size_t)l * 192 * 192, wo_lo + (size_t)l * 192 * 192,
            cN, 192, 192, t2b, nullptr, nullptr, nullptr, 0,
            nullptr, nullptr, nullptr, nullptr);
        ln_kernel<<<cN, 192>>>(hb, t2b, bo + l * cHID, ln1_g + l * cHID, ln1_b + l * cHID);
        // FF1: relu(h@W1+b1) -> half split t1
        gemm_mma<1><<<dim3(MB, 4), 256, GSMEM>>>(
            h_hi, h_lo, wff1_hi + (size_t)l * 384 * 192, wff1_lo + (size_t)l * 384 * 192,
            cN, 192, 384, nullptr, t1_hi, t1_lo, b_ff1 + l * cFFN, 1,
            nullptr, nullptr, nullptr, nullptr);
        // FF2: t1@W2 + b2 -> fp32 t2
        gemm_mma<0><<<dim3(MB, 2), 256, GSMEM>>>(
            t1_hi, t1_lo, wff2_hi + (size_t)l * 192 * 384, wff2_lo + (size_t)l * 192 * 384,
            cN, 384, 192, t2b, nullptr, nullptr, b_ff2 + l * cHID, 0,
            nullptr, nullptr, nullptr, nullptr);
        ln_kernel<<<cN, 192>>>(hb, t2b, nullptr, ln2_g + l * cHID, ln2_b + l * cHID);
    }

    // edge head node GEMMs: eA = h@W_e1[0:192]+b_e1 ; eB = h@W_e1[192:384]
    gemm_mma<0><<<dim3(MB, 2), 256, GSMEM>>>(
        h_hi, h_lo, weA_hi, weA_lo, cN, 192, 192, eAb, nullptr, nullptr, b_e1, 0,
        nullptr, nullptr, nullptr, nullptr);
    gemm_mma<0><<<dim3(MB, 2), 256, GSMEM>>>(
        h_hi, h_lo, weB_hi, weB_lo, cN, 192, 192, eBb, nullptr, nullptr, nullptr, 0,
        nullptr, nullptr, nullptr, nullptr);
    // per-edge z1 (half split)
    z1_kernel<<<cE / 2, 384>>>(eattr, ei, W_e1);
    // edge GEMM + fused relu/W_e3 reduction -> out[E]
    gemm_mma<2><<<dim3(cE / 128, 1), 256, GSMEM>>>(
        z1_hi, z1_lo, we2_hi, we2_lo, cE, 192, 96, nullptr, nullptr, nullptr, nullptr, 0,
        W_e3, b_e2, b_e3, out);
}